// round 15
// baseline (speedup 1.0000x reference)
#include <cuda_runtime.h>

#define NN   28      // nodes
#define NA   32      // padded A row stride
#define ND   64      // duplicated-pair A row stride (floats)
#define RPB  128     // rows per block
#define TPB  256     // threads: q = t&7 (comps), g = t>>3 (row-group of 4)
#define SR   132     // transposed x/z stage row stride (528B, 16B-aligned)

typedef unsigned long long ull;

// packed fp32x2 FMA (sm_103a): d = a*b + c elementwise on register pairs
__device__ __forceinline__ ull fma2(ull a, ull b, ull c) {
    ull d;
    asm("fma.rn.f32x2 %0, %1, %2, %3;" : "=l"(d) : "l"(a), "l"(b), "l"(c));
    return d;
}
__device__ __forceinline__ float2 unpk(ull v) {
    float2 f;
    asm("mov.b64 {%0, %1}, %2;" : "=f"(f.x), "=f"(f.y) : "l"(v));
    return f;
}

// ---------------------------------------------------------------------------
// Fused kernel. Per block: stage 128 x-rows transposed, build normalized
// adjacency in shared (dtype-probed edge_index), duplicate A entries into
// pairs for f32x2 math, collapse MLP to (cp,cn), compute out = A.f(A.x)+b2.
// Thread (q=t&7, g=t>>3): comps [4q,4q+4) of rows [4g,4g+4).
// Accumulators packed over row pairs: acc01 = rows (4g,4g+1), acc23 = (4g+2,4g+3).
// ---------------------------------------------------------------------------
__global__ void __launch_bounds__(TPB, 4) gcn_fused_kernel(
    const float* __restrict__ x, float* __restrict__ out,
    const int* __restrict__ ei32, int n_elems,
    const float* __restrict__ W1, const float* __restrict__ b1,
    const float* __restrict__ W2, const float* __restrict__ b2,
    int H, int B)
{
    __shared__ __align__(16) float As[NN * NA];   // As[s*NA+d] = A[d][s]
    __shared__ __align__(16) float Asd[NN * ND];  // dup pairs: [s*ND+2d] = [.. +1] = A[d][s]
    __shared__ __align__(16) float xs[NN * SR];   // transposed x, then z
    __shared__ float deg[NN];
    __shared__ float dinv[NN];
    __shared__ float wred[128];
    __shared__ float s_cp, s_cn;

    const int t  = threadIdx.x;
    const int q  = t & 7;             // comp block: comps [4q, 4q+4)
    const int g  = t >> 3;            // row-group 0..31
    const int r0 = g * 4;

    // ---- init shared ----
    if (t < NN) deg[t] = 1.0f;        // self-loop contributes 1
    for (int i = t; i < NN * NA; i += TPB) As[i] = 0.0f;

    // ---- stage x transposed: xs[c*SR + r] = x[row r, comp c] ----
    const long long rowbase = (long long)blockIdx.x * RPB;
    int nrows = (int)(B - rowbase); if (nrows > RPB) nrows = RPB;
    const float* gx = x + rowbase * NN;
    for (int i = t; i < nrows * NN; i += TPB) {
        int r = i / NN, c = i - r * NN;
        xs[c * SR + r] = gx[i];
    }

    // ---- dtype probe: int64 LE with ids <28 has all-zero odd int32 words ----
    int found = 0;
    for (int i = 2 * t + 1; i < n_elems; i += 2 * TPB)
        if (ei32[i] != 0) found = 1;
    const int is32 = __syncthreads_or(found);

    const int E = n_elems / 2;
    const int stride  = is32 ? 1 : 2;
    const int dstbase = is32 ? E : 2 * E;

    // ---- degrees ----
    for (int e = t; e < E; e += TPB) {
        int d = ei32[dstbase + stride * e];
        if (d >= 0 && d < NN) atomicAdd(&deg[d], 1.0f);
    }
    __syncthreads();
    if (t < NN) dinv[t] = deg[t] > 0.0f ? rsqrtf(deg[t]) : 0.0f;
    __syncthreads();

    // ---- adjacency, built transposed: As[s*NA + d] += dinv_s*dinv_d ----
    for (int e = t; e < E; e += TPB) {
        int s = ei32[stride * e];
        int d = ei32[dstbase + stride * e];
        if (s >= 0 && s < NN && d >= 0 && d < NN)
            atomicAdd(&As[s * NA + d], dinv[s] * dinv[d]);
    }
    if (t < NN) atomicAdd(&As[t * NA + t], dinv[t] * dinv[t]);

    // ---- MLP collapse partials ----
    int gflag = 0;
    if (t < 64) {
        float p = 0.0f, n = 0.0f;
        for (int o = t; o < H; o += 64) {
            float w1 = W1[o], w2 = W2[o];
            if (w1 > 0.0f) p += w1 * w2;
            else           n += w1 * w2;
            if (b1[o] != 0.0f) gflag = 1;
        }
        wred[t] = p; wred[64 + t] = n;
    }
    const int general = __syncthreads_or(gflag);   // fences As atomics too

    // ---- expand A into duplicated pairs; reduce cp/cn ----
    for (int i = t; i < NN * NA; i += TPB) {
        int s = i >> 5, d = i & 31;
        float v = As[i];
        Asd[s * ND + 2 * d]     = v;
        Asd[s * ND + 2 * d + 1] = v;
    }
    if (t == 0) {
        float cpa = 0.0f, cna = 0.0f;
        #pragma unroll
        for (int i = 0; i < 64; i++) { cpa += wred[i]; cna += wred[64 + i]; }
        s_cp = cpa; s_cn = cna;
    }
    __syncthreads();
    const float cp = s_cp, cn = s_cn, b2v = b2[0];

    // ---- matvec 1: packed acc over row pairs ----
    ull acc01[4], acc23[4];
    #pragma unroll
    for (int j = 0; j < 4; j++) { acc01[j] = 0ull; acc23[j] = 0ull; }

    const float* adp = Asd + q * 8;   // this thread's 4 dup-pairs (32B)

    #pragma unroll
    for (int s = 0; s < NN; s++) {
        const ulonglong2 xp = *(const ulonglong2*)(xs + s * SR + r0);
        const ulonglong2 aA = *(const ulonglong2*)(adp + s * ND);
        const ulonglong2 aB = *(const ulonglong2*)(adp + s * ND + 4);
        acc01[0] = fma2(aA.x, xp.x, acc01[0]); acc23[0] = fma2(aA.x, xp.y, acc23[0]);
        acc01[1] = fma2(aA.y, xp.x, acc01[1]); acc23[1] = fma2(aA.y, xp.y, acc23[1]);
        acc01[2] = fma2(aB.x, xp.x, acc01[2]); acc23[2] = fma2(aB.x, xp.y, acc23[2]);
        acc01[3] = fma2(aB.y, xp.x, acc01[3]); acc23[3] = fma2(aB.y, xp.y, acc23[3]);
    }

    // ---- z = f(y) (scalar on unpacked pairs) ----
    float z01[4][2], z23[4][2];
    #pragma unroll
    for (int j = 0; j < 4; j++) {
        float2 a = unpk(acc01[j]), b = unpk(acc23[j]);
        z01[j][0] = a.x; z01[j][1] = a.y;
        z23[j][0] = b.x; z23[j][1] = b.y;
    }
    if (!general) {
        #pragma unroll
        for (int j = 0; j < 4; j++) {
            #pragma unroll
            for (int k = 0; k < 2; k++) {
                z01[j][k] = cp * fmaxf(z01[j][k], 0.0f) + cn * fminf(z01[j][k], 0.0f);
                z23[j][k] = cp * fmaxf(z23[j][k], 0.0f) + cn * fminf(z23[j][k], 0.0f);
            }
        }
    } else {
        #pragma unroll
        for (int j = 0; j < 4; j++) {
            #pragma unroll
            for (int k = 0; k < 2; k++) {
                float v0 = z01[j][k], v1 = z23[j][k], a0 = 0.0f, a1 = 0.0f;
                for (int o = 0; o < H; o++) {
                    float w1 = W1[o], bb = b1[o], w2 = W2[o];
                    a0 = fmaf(w2, fmaxf(fmaf(w1, v0, bb), 0.0f), a0);
                    a1 = fmaf(w2, fmaxf(fmaf(w1, v1, bb), 0.0f), a1);
                }
                z01[j][k] = a0; z23[j][k] = a1;
            }
        }
    }

    __syncthreads();   // matvec-1 reads of xs done before z overwrite

    // ---- publish z transposed (q=7 owns padding comps 28..31: skip) ----
    if (q < 7) {
        #pragma unroll
        for (int j = 0; j < 4; j++) {
            int d = q * 4 + j;
            *(float4*)(xs + d * SR + r0) =
                make_float4(z01[j][0], z01[j][1], z23[j][0], z23[j][1]);
        }
    }
    __syncthreads();

    // ---- matvec 2 ----
    #pragma unroll
    for (int j = 0; j < 4; j++) { acc01[j] = 0ull; acc23[j] = 0ull; }

    #pragma unroll
    for (int s = 0; s < NN; s++) {
        const ulonglong2 zp = *(const ulonglong2*)(xs + s * SR + r0);
        const ulonglong2 aA = *(const ulonglong2*)(adp + s * ND);
        const ulonglong2 aB = *(const ulonglong2*)(adp + s * ND + 4);
        acc01[0] = fma2(aA.x, zp.x, acc01[0]); acc23[0] = fma2(aA.x, zp.y, acc23[0]);
        acc01[1] = fma2(aA.y, zp.x, acc01[1]); acc23[1] = fma2(aA.y, zp.y, acc23[1]);
        acc01[2] = fma2(aB.x, zp.x, acc01[2]); acc23[2] = fma2(aB.x, zp.y, acc23[2]);
        acc01[3] = fma2(aB.y, zp.x, acc01[3]); acc23[3] = fma2(aB.y, zp.y, acc23[3]);
    }

    // ---- add bias, store comps [4q,4q+4) of rows r0..r0+3 ----
    if (q < 7) {
        float o0[4], o1[4], o2[4], o3[4];
        #pragma unroll
        for (int j = 0; j < 4; j++) {
            float2 a = unpk(acc01[j]), b = unpk(acc23[j]);
            o0[j] = a.x + b2v; o1[j] = a.y + b2v;
            o2[j] = b.x + b2v; o3[j] = b.y + b2v;
        }
        #pragma unroll
        for (int rw = 0; rw < 4; rw++) {
            int lr = r0 + rw;
            if (lr < nrows) {
                float* op = out + (rowbase + lr) * NN + q * 4;
                const float* src = (rw == 0) ? o0 : (rw == 1) ? o1 : (rw == 2) ? o2 : o3;
                *(float4*)op = make_float4(src[0], src[1], src[2], src[3]);
            }
        }
    }
}

extern "C" void kernel_launch(void* const* d_in, const int* in_sizes, int n_in,
                              void* d_out, int out_size)
{
    const float* x  = (const float*)d_in[0];
    const int*   ei = (const int*)d_in[1];     // int32 view; dtype probed on-device
    const float* W1 = (const float*)d_in[2];
    const float* b1 = (const float*)d_in[3];
    const float* W2 = (const float*)d_in[4];
    const float* b2 = (const float*)d_in[5];
    float* out = (float*)d_out;

    int B = in_sizes[0] / NN;
    int n_edge_elems = in_sizes[1];
    int H = in_sizes[3];

    int grid = (B + RPB - 1) / RPB;
    gcn_fused_kernel<<<grid, TPB>>>(x, out, ei, n_edge_elems,
                                    W1, b1, W2, b2, H, B);
}

// round 17
// speedup vs baseline: 1.1935x; 1.1935x over previous
#include <cuda_runtime.h>

#define NN   28      // nodes
#define NA   32      // padded A row stride
#define RPB  64      // rows per block
#define TPB  256     // threads: q = t&7 (comps), g = t>>3 (row-pair 0..31)
#define SR   66      // transposed x/z stage row stride (even -> 8B aligned pairs)

// pick component of a float2/float4 with a compile-time constant index
__device__ __forceinline__ float f4c(const float4& v, int c) {
    return (c == 0) ? v.x : (c == 1) ? v.y : (c == 2) ? v.z : v.w;
}

// ---------------------------------------------------------------------------
// Fused kernel (R10 structure, 2 rows/thread for 2x warp count).
// Per block: stage 64 x-rows transposed, build normalized adjacency in shared
// (dtype-probed edge_index), collapse MLP to (cp,cn), out = A . f(A . x) + b2.
// Thread (q=t&7, g=t>>3): comps [4q,4q+4) of rows [2g,2g+2).
// Inner loop per s: LDS.64 (2 rows' x) + LDS.128 (4 A comps) + 8 FMA.
// ---------------------------------------------------------------------------
__global__ void __launch_bounds__(TPB, 6) gcn_fused_kernel(
    const float* __restrict__ x, float* __restrict__ out,
    const int* __restrict__ ei32, int n_elems,
    const float* __restrict__ W1, const float* __restrict__ b1,
    const float* __restrict__ W2, const float* __restrict__ b2,
    int H, int B)
{
    __shared__ __align__(16) float As[NN * NA];   // As[s*NA+d] = A[d][s]
    __shared__ __align__(16) float xs[NN * SR];   // transposed x, then z
    __shared__ float deg[NN];
    __shared__ float dinv[NN];
    __shared__ float wred[128];
    __shared__ float s_cp, s_cn;

    const int t  = threadIdx.x;
    const int q  = t & 7;             // comp block: comps [4q, 4q+4)
    const int g  = t >> 3;            // row-pair 0..31
    const int r0 = g * 2;

    // ---- init shared ----
    if (t < NN) deg[t] = 1.0f;        // self-loop contributes 1
    for (int i = t; i < NN * NA; i += TPB) As[i] = 0.0f;

    // ---- stage x transposed: xs[c*SR + r] = x[row r, comp c] ----
    const long long rowbase = (long long)blockIdx.x * RPB;
    int nrows = (int)(B - rowbase); if (nrows > RPB) nrows = RPB;
    const float* gx = x + rowbase * NN;
    for (int i = t; i < nrows * NN; i += TPB) {
        int r = i / NN, c = i - r * NN;
        xs[c * SR + r] = gx[i];
    }

    // ---- dtype probe: int64 LE with ids <28 has all-zero odd int32 words ----
    int found = 0;
    for (int i = 2 * t + 1; i < n_elems; i += 2 * TPB)
        if (ei32[i] != 0) found = 1;
    const int is32 = __syncthreads_or(found);

    const int E = n_elems / 2;
    const int stride  = is32 ? 1 : 2;
    const int dstbase = is32 ? E : 2 * E;

    // ---- degrees ----
    for (int e = t; e < E; e += TPB) {
        int d = ei32[dstbase + stride * e];
        if (d >= 0 && d < NN) atomicAdd(&deg[d], 1.0f);
    }
    __syncthreads();
    if (t < NN) dinv[t] = deg[t] > 0.0f ? rsqrtf(deg[t]) : 0.0f;
    __syncthreads();

    // ---- adjacency, built transposed: As[s*NA + d] += dinv_s*dinv_d ----
    for (int e = t; e < E; e += TPB) {
        int s = ei32[stride * e];
        int d = ei32[dstbase + stride * e];
        if (s >= 0 && s < NN && d >= 0 && d < NN)
            atomicAdd(&As[s * NA + d], dinv[s] * dinv[d]);
    }
    if (t < NN) atomicAdd(&As[t * NA + t], dinv[t] * dinv[t]);

    // ---- MLP collapse: cp/cn partials ----
    int gflag = 0;
    if (t < 64) {
        float p = 0.0f, n = 0.0f;
        for (int o = t; o < H; o += 64) {
            float w1 = W1[o], w2 = W2[o];
            if (w1 > 0.0f) p += w1 * w2;
            else           n += w1 * w2;
            if (b1[o] != 0.0f) gflag = 1;
        }
        wred[t] = p; wred[64 + t] = n;
    }
    const int general = __syncthreads_or(gflag);  // fences As atomics too
    if (t == 0) {
        float cpa = 0.0f, cna = 0.0f;
        #pragma unroll
        for (int i = 0; i < 64; i++) { cpa += wred[i]; cna += wred[64 + i]; }
        s_cp = cpa; s_cn = cna;
    }
    __syncthreads();
    const float cp = s_cp, cn = s_cn, b2v = b2[0];

    const float* ap = As + q * 4;     // this thread's 4-wide A slice

    // ---- matvec 1: acc[rw][j] = sum_s A[s][4q+j] * x[r0+rw][s] ----
    float acc[2][4];
    #pragma unroll
    for (int rw = 0; rw < 2; rw++)
        #pragma unroll
        for (int j = 0; j < 4; j++) acc[rw][j] = 0.0f;

    #pragma unroll
    for (int s = 0; s < NN; s++) {
        const float2 xv = *(const float2*)(xs + s * SR + r0);  // 2 rows at s
        const float4 a  = *(const float4*)(ap + s * NA);       // 4 comps at s
        acc[0][0] = fmaf(a.x, xv.x, acc[0][0]);
        acc[0][1] = fmaf(a.y, xv.x, acc[0][1]);
        acc[0][2] = fmaf(a.z, xv.x, acc[0][2]);
        acc[0][3] = fmaf(a.w, xv.x, acc[0][3]);
        acc[1][0] = fmaf(a.x, xv.y, acc[1][0]);
        acc[1][1] = fmaf(a.y, xv.y, acc[1][1]);
        acc[1][2] = fmaf(a.z, xv.y, acc[1][2]);
        acc[1][3] = fmaf(a.w, xv.y, acc[1][3]);
    }

    // ---- z = f(y) ----
    if (!general) {
        #pragma unroll
        for (int rw = 0; rw < 2; rw++)
            #pragma unroll
            for (int j = 0; j < 4; j++)
                acc[rw][j] = cp * fmaxf(acc[rw][j], 0.0f)
                           + cn * fminf(acc[rw][j], 0.0f);
    } else {
        // cold fallback (b1 != 0): exact per-element MLP
        #pragma unroll
        for (int rw = 0; rw < 2; rw++)
            #pragma unroll
            for (int j = 0; j < 4; j++) {
                float v = acc[rw][j], a2 = 0.0f;
                for (int o = 0; o < H; o++)
                    a2 = fmaf(W2[o], fmaxf(fmaf(W1[o], v, b1[o]), 0.0f), a2);
                acc[rw][j] = a2;
            }
    }

    __syncthreads();   // matvec-1 reads of xs complete before z overwrite

    // ---- publish z transposed (q=7 owns padding comps 28..31: skip) ----
    if (q < 7) {
        #pragma unroll
        for (int j = 0; j < 4; j++) {
            int d = q * 4 + j;
            *(float2*)(xs + d * SR + r0) = make_float2(acc[0][j], acc[1][j]);
        }
    }
    __syncthreads();

    // ---- matvec 2: acc[rw][j] = b2 + sum_s A[s][4q+j] * z[r0+rw][s] ----
    #pragma unroll
    for (int rw = 0; rw < 2; rw++)
        #pragma unroll
        for (int j = 0; j < 4; j++) acc[rw][j] = b2v;

    #pragma unroll
    for (int s = 0; s < NN; s++) {
        const float2 zv = *(const float2*)(xs + s * SR + r0);
        const float4 a  = *(const float4*)(ap + s * NA);
        acc[0][0] = fmaf(a.x, zv.x, acc[0][0]);
        acc[0][1] = fmaf(a.y, zv.x, acc[0][1]);
        acc[0][2] = fmaf(a.z, zv.x, acc[0][2]);
        acc[0][3] = fmaf(a.w, zv.x, acc[0][3]);
        acc[1][0] = fmaf(a.x, zv.y, acc[1][0]);
        acc[1][1] = fmaf(a.y, zv.y, acc[1][1]);
        acc[1][2] = fmaf(a.z, zv.y, acc[1][2]);
        acc[1][3] = fmaf(a.w, zv.y, acc[1][3]);
    }

    // ---- direct coalesced stores: comps [4q,4q+4) of rows r0, r0+1 ----
    if (q * 4 < NN) {
        #pragma unroll
        for (int rw = 0; rw < 2; rw++) {
            int lr = r0 + rw;
            if (lr < nrows) {
                float* op = out + (rowbase + lr) * NN + q * 4;
                *(float4*)op = make_float4(acc[rw][0], acc[rw][1],
                                           acc[rw][2], acc[rw][3]);
            }
        }
    }
}

extern "C" void kernel_launch(void* const* d_in, const int* in_sizes, int n_in,
                              void* d_out, int out_size)
{
    const float* x  = (const float*)d_in[0];
    const int*   ei = (const int*)d_in[1];     // int32 view; dtype probed on-device
    const float* W1 = (const float*)d_in[2];
    const float* b1 = (const float*)d_in[3];
    const float* W2 = (const float*)d_in[4];
    const float* b2 = (const float*)d_in[5];
    float* out = (float*)d_out;

    int B = in_sizes[0] / NN;
    int n_edge_elems = in_sizes[1];
    int H = in_sizes[3];

    int grid = (B + RPB - 1) / RPB;
    gcn_fused_kernel<<<grid, TPB>>>(x, out, ei, n_edge_elems,
                                    W1, b1, W2, b2, H, B);
}